// round 1
// baseline (speedup 1.0000x reference)
#include <cuda_runtime.h>

// Input order (metadata.txt / setup_inputs dict order):
// 0: x      [2,192,88,133] f32
// 1: W_lin  [133,24]
// 2: b_lin  [24]
// 3: W_qkv  [24,72]
// 4: b_qkv  [72]
// 5: rpb    [4,49,49]
// 6: W_proj [24,24]
// 7: b_proj [24]
// output: [2,192,88,24] f32

#define BB   2
#define HT   192
#define WD   88
#define FIN  133
#define CC   24
#define NH   4
#define DH   6
#define WIN  25
#define NPIX (BB*HT*WD)   // 33792
#define RPBW (2*WIN - 1)  // 49

// Scratch (device globals: allocation-free)
__device__ float g_h[NPIX*CC];
__device__ float g_q[NPIX*CC];   // layout [b][row][ch(=h*6+d)][col]
__device__ float g_k[NPIX*CC];   // layout [b][row][ch][col]
__device__ float g_v[NPIX*CC];   // layout [b][row][ch][col]
__device__ float g_attn[NPIX*CC];// layout [b][row][col][ch]

// ---------------------------------------------------------------------------
// FMA-only exp(x) for x <= ~0 (clamped at -30). Rel err ~2.4e-6.
// Avoids MUFU (which would be the throughput bottleneck at 169M exps).
// ---------------------------------------------------------------------------
__device__ __forceinline__ float fexp(float x) {
    float t = fmaxf(x * 1.4426950408889634f, -30.0f);   // log2(e)*x, clamped
    float r = t + 12582912.0f;                          // round-to-nearest int
    int   n = __float_as_int(r);                        // 0x4B400000 + round(t)
    float f = t - (r - 12582912.0f);                    // frac in [-0.5, 0.5]
    // 2^f degree-5 (Taylor in ln2*f)
    float p = 1.3333558146e-3f;
    p = fmaf(p, f, 9.6181291076e-3f);
    p = fmaf(p, f, 5.5504108665e-2f);
    p = fmaf(p, f, 2.4022650696e-1f);
    p = fmaf(p, f, 6.9314718056e-1f);
    p = fmaf(p, f, 1.0f);
    return p * __int_as_float((n - 0x4B400000 + 127) << 23);
}

// ---------------------------------------------------------------------------
// Kernel 1: h = relu(x @ W_lin + b_lin). One thread per output element.
// ---------------------------------------------------------------------------
__global__ void k_linrelu(const float* __restrict__ x,
                          const float* __restrict__ W,
                          const float* __restrict__ b) {
    int t = blockIdx.x * blockDim.x + threadIdx.x;
    if (t >= NPIX*CC) return;
    int row = t / CC, c = t % CC;
    const float* xr = x + (size_t)row * FIN;
    float acc = b[c];
    #pragma unroll 7
    for (int f = 0; f < FIN; ++f) acc = fmaf(xr[f], W[f*CC + c], acc);
    g_h[t] = fmaxf(acc, 0.0f);
}

// ---------------------------------------------------------------------------
// Kernel 2: qkv per (b,i) row. q pre-scaled by dh^-0.5; q/k/v written d-major.
// ---------------------------------------------------------------------------
__global__ void k_qkv(const float* __restrict__ Wq,
                      const float* __restrict__ bq) {
    __shared__ float hs[WD][CC + 1];   // +1 pad: conflict-free stride 25
    __shared__ float ws[CC][3*CC];
    int bi  = blockIdx.x;              // b*192 + i
    int tid = threadIdx.x;             // 256 threads

    for (int idx = tid; idx < WD*CC; idx += 256)
        hs[idx / CC][idx % CC] = g_h[(size_t)bi * WD * CC + idx];
    for (int idx = tid; idx < CC*3*CC; idx += 256)
        ws[idx / (3*CC)][idx % (3*CC)] = Wq[idx];
    __syncthreads();

    for (int o = tid; o < WD*3*CC; o += 256) {
        int j = o % WD, cfull = o / WD;          // cfull in [0,72)
        float acc = bq[cfull];
        #pragma unroll
        for (int u = 0; u < CC; ++u) acc = fmaf(hs[j][u], ws[u][cfull], acc);
        int which = cfull / CC, ch = cfull % CC;
        float* dst;
        if (which == 0) { acc *= 0.40824829046386302f; dst = g_q; }
        else if (which == 1) dst = g_k;
        else dst = g_v;
        dst[((size_t)bi * CC + ch) * WD + j] = acc;
    }
}

// ---------------------------------------------------------------------------
// Kernel 3: neighborhood attention, one block per (b,i), thread = (j, head).
// Streams the 25 key rows through smem; online softmax with a per-row
// register score buffer (single rescale per window row).
// ---------------------------------------------------------------------------
__global__ void __launch_bounds__(352) k_attn(const float* __restrict__ rpb) {
    __shared__ float bias_s[NH * WIN * RPBW];  // 4*25*49 = 4900 f (19.6 KB)
    __shared__ float k_s[CC * WD];             // 2112 f
    __shared__ float v_s[CC * WD];             // 2112 f

    int blk = blockIdx.x;
    int b = blk / HT, i = blk % HT;
    int tid = threadIdx.x;
    int j = tid % WD, h = tid / WD;
    int h6 = h * DH;

    int sii = min(max(i - WIN/2, 0), HT - WIN);
    int bii = sii - i + WIN - 1;               // block-uniform
    int sjj = min(max(j - WIN/2, 0), WD - WIN);
    int bjj = sjj - j + WIN - 1;

    // Stage the rpb slice for this i: rows bii..bii+24 for all heads.
    for (int idx = tid; idx < NH*WIN*RPBW; idx += 352) {
        int hh = idx / (WIN*RPBW);
        bias_s[idx] = rpb[idx + hh * (RPBW*RPBW - WIN*RPBW) + bii * RPBW];
    }

    // q for this (j, head): 6 coalesced strided loads
    float qv[DH];
    const float* qbase = g_q + (((size_t)(b*HT + i)) * CC + h6) * WD + j;
    #pragma unroll
    for (int d = 0; d < DH; ++d) qv[d] = qbase[d * WD];

    float m = -1e30f, l = 0.0f, acc[DH];
    #pragma unroll
    for (int d = 0; d < DH; ++d) acc[d] = 0.0f;

    for (int ki = 0; ki < WIN; ++ki) {
        __syncthreads();   // previous iteration's readers done
        size_t krow = ((size_t)(b*HT + sii + ki)) * CC * WD;
        for (int idx = tid; idx < CC*WD; idx += 352) {   // 2112/352 = 6 exact
            k_s[idx] = g_k[krow + idx];
            v_s[idx] = g_v[krow + idx];
        }
        __syncthreads();

        const float* kb = k_s + h6 * WD + sjj;
        const float* vb = v_s + h6 * WD + sjj;
        const float* br = bias_s + (h * WIN + ki) * RPBW + bjj;

        float s[WIN];
        #pragma unroll
        for (int kj = 0; kj < WIN; ++kj) {
            float sc = br[kj];
            #pragma unroll
            for (int d = 0; d < DH; ++d) sc = fmaf(qv[d], kb[d*WD + kj], sc);
            s[kj] = sc;
        }
        float rmax = s[0];
        #pragma unroll
        for (int kj = 1; kj < WIN; ++kj) rmax = fmaxf(rmax, s[kj]);

        float mnew = fmaxf(m, rmax);
        float corr = fexp(m - mnew);
        l *= corr;
        #pragma unroll
        for (int d = 0; d < DH; ++d) acc[d] *= corr;

        #pragma unroll
        for (int kj = 0; kj < WIN; ++kj) {
            float p = fexp(s[kj] - mnew);
            l += p;
            #pragma unroll
            for (int d = 0; d < DH; ++d)
                acc[d] = fmaf(p, vb[d*WD + kj], acc[d]);
        }
        m = mnew;
    }

    float inv = __fdividef(1.0f, l);
    float* ob = g_attn + (((size_t)(b*HT + i)) * WD + j) * CC + h6;
    #pragma unroll
    for (int d = 0; d < DH; ++d) ob[d] = acc[d] * inv;
}

// ---------------------------------------------------------------------------
// Kernel 4: out = attn @ W_proj + b_proj. use_ext -> write d_out else g_h.
// ---------------------------------------------------------------------------
__global__ void k_proj(const float* __restrict__ Wp,
                       const float* __restrict__ bp,
                       float* __restrict__ ext_out, int use_ext) {
    int t = blockIdx.x * blockDim.x + threadIdx.x;
    if (t >= NPIX*CC) return;
    int row = t / CC, c = t % CC;
    const float* ar = g_attn + (size_t)row * CC;
    float acc = bp[c];
    #pragma unroll
    for (int u = 0; u < CC; ++u) acc = fmaf(ar[u], Wp[u*CC + c], acc);
    float* dst = use_ext ? ext_out : g_h;
    dst[t] = acc;
}

// ---------------------------------------------------------------------------
extern "C" void kernel_launch(void* const* d_in, const int* in_sizes, int n_in,
                              void* d_out, int out_size) {
    (void)in_sizes; (void)n_in; (void)out_size;
    const float* x      = (const float*)d_in[0];
    const float* W_lin  = (const float*)d_in[1];
    const float* b_lin  = (const float*)d_in[2];
    const float* W_qkv  = (const float*)d_in[3];
    const float* b_qkv  = (const float*)d_in[4];
    const float* rpb    = (const float*)d_in[5];
    const float* W_proj = (const float*)d_in[6];
    const float* b_proj = (const float*)d_in[7];
    float* out = (float*)d_out;

    const int nElem = NPIX * CC;
    k_linrelu<<<(nElem + 255)/256, 256>>>(x, W_lin, b_lin);
    for (int L = 0; L < 2; ++L) {
        k_qkv <<<BB*HT, 256>>>(W_qkv, b_qkv);
        k_attn<<<BB*HT, 352>>>(rpb);
        k_proj<<<(nElem + 255)/256, 256>>>(W_proj, b_proj, out, L == 1 ? 1 : 0);
    }
}